// round 3
// baseline (speedup 1.0000x reference)
#include <cuda_runtime.h>
#include <math.h>

// Problem constants
constexpr int Bn = 1024;   // batch
constexpr int Hn = 256;    // hidden
constexpr int Gn = 768;    // 3*H (gate rows)
constexpr int On = 512;    // output rows
constexpr int Tn = 60;     // timesteps
constexpr int Cn = 15;     // cameras

constexpr int CH     = 32;   // sample chunk staged in smem
constexpr int WS_STR = 260;  // padded smem row stride (floats) -> conflict-free LDS.128

// -------- device scratch (static: allocation-free) --------
__device__ float g_gi[Bn * Gn];   // input-gate preactivations (+b_ih), computed once
__device__ float g_gh[Bn * Gn];   // hidden-gate preactivations (+b_hh), per step
__device__ float g_h [Bn * Hn];   // hidden state
__device__ int   g_cnt [Cn];
__device__ int   g_off [Cn];
__device__ int   g_list[Bn];      // sample indices grouped by camera

__device__ __forceinline__ void ffma2(unsigned long long &acc,
                                      unsigned long long a,
                                      unsigned long long b) {
    asm("fma.rn.f32x2 %0, %1, %2, %0;" : "+l"(acc) : "l"(a), "l"(b));
}
__device__ __forceinline__ float2 upk(unsigned long long v) {
    float2 f;
    asm("mov.b64 {%0, %1}, %2;" : "=f"(f.x), "=f"(f.y) : "l"(v));
    return f;
}
__device__ __forceinline__ float sigmoidf(float x) {
    return 1.0f / (1.0f + expf(-x));
}

// -------- group samples by camera --------
__global__ void group_kernel(const int* __restrict__ cam) {
    __shared__ int cnt[Cn], off[Cn], cur[Cn];
    int tid = threadIdx.x;
    if (tid < Cn) { cnt[tid] = 0; cur[tid] = 0; }
    __syncthreads();
    int c = cam[tid];
    atomicAdd(&cnt[c], 1);
    __syncthreads();
    if (tid == 0) {
        int s = 0;
        for (int i = 0; i < Cn; i++) { off[i] = s; s += cnt[i]; }
    }
    __syncthreads();
    if (tid < Cn) { g_cnt[tid] = cnt[tid]; g_off[tid] = off[tid]; }
    int p = atomicAdd(&cur[c], 1);
    g_list[off[c] + p] = tid;
}

// -------- init: h0 = 0, gh0 = b_hh (since h0 @ Whh == 0) --------
__global__ void init_kernel(const int* __restrict__ cam,
                            const float* __restrict__ b_hh) {
    int b = blockIdx.x, j = threadIdx.x;
    g_h[b * Hn + j] = 0.0f;
    int c = cam[b];
    g_gh[b * Gn + j]       = b_hh[c * Gn + j];
    g_gh[b * Gn + 256 + j] = b_hh[c * Gn + 256 + j];
    g_gh[b * Gn + 512 + j] = b_hh[c * Gn + 512 + j];
}

// -------- GRU elementwise: h <- GRU(gi, gh, h) --------
__global__ void gru_kernel() {
    int b = blockIdx.x, j = threadIdx.x;
    const float* gi = g_gi + b * Gn;
    const float* gh = g_gh + b * Gn;
    float r = sigmoidf(gi[j]       + gh[j]);
    float z = sigmoidf(gi[256 + j] + gh[256 + j]);
    float n = tanhf(gi[512 + j] + r * gh[512 + j]);
    float h = g_h[b * Hn + j];
    g_h[b * Hn + j] = (1.0f - z) * n + z * h;
}

// -------- tiled per-camera GEMM --------
// STEP=false: gi = x @ W_ih^T + b_ih            (TILE=128, 6 tiles/camera)
// STEP=true : [gh ; out_t] = h @ [W_hh; Wc]^T   (TILE=160, 8 tiles/camera)
//   rows < 768 -> g_gh (+ b_hh); rows >= 768 -> sigmoid(. + bc) -> out[:,:,t-1]
template <int TILE, bool STEP>
__global__ void __launch_bounds__((TILE / 32) * 2 * 32, 1)
gemm_tile(const float* __restrict__ Wmain, const float* __restrict__ Wcp,
          const float* __restrict__ bmain, const float* __restrict__ bcp,
          const float* __restrict__ xin, float* __restrict__ dout, int t) {
    constexpr int RTOT = STEP ? (Gn + On) : Gn;
    constexpr int NT   = RTOT / TILE;
    constexpr int NTHR = (TILE / 32) * 2 * 32;

    extern __shared__ float sm[];
    float* Ws   = sm;                      // TILE x WS_STR
    float* Hs   = sm + TILE * WS_STR;      // CH x Hn
    int*   Sidx = (int*)(Hs + CH * Hn);    // CH

    int tid    = threadIdx.x;
    int camidx = blockIdx.x / NT;
    int tile   = blockIdx.x % NT;
    int row0   = tile * TILE;

    const float* vin = STEP ? g_h : xin;
    float*       oa  = STEP ? g_gh : g_gi;

    // stage weight tile: each row read exactly once per step, reused across chunks
    for (int i = tid; i < TILE * 64; i += NTHR) {
        int r = i >> 6, kq = i & 63;
        int rr = row0 + r;
        const float4* src;
        if (!STEP || rr < Gn)
            src = (const float4*)(Wmain + ((size_t)camidx * Gn + rr) * (size_t)Hn);
        else
            src = (const float4*)(Wcp + ((size_t)camidx * On + (rr - Gn)) * (size_t)Hn);
        float4 v = src[kq];
        *(float4*)(Ws + r * WS_STR + (kq << 2)) = v;
    }

    int mcount = g_cnt[camidx];
    int moff   = g_off[camidx];

    int lane = tid & 31, w = tid >> 5;
    int rg = w >> 1, half = w & 1;            // warp = 32 rows x 16 samples
    int rloc = rg * 32 + lane;
    const float* wrow  = Ws + rloc * WS_STR;
    const float* hbase = Hs + half * 16 * Hn;

    for (int m0 = 0; m0 < mcount; m0 += CH) {
        int mchunk = min(CH, mcount - m0);
        __syncthreads();  // prior chunk done with Hs/Sidx
        if (tid < CH) Sidx[tid] = (tid < mchunk) ? g_list[moff + m0 + tid] : -1;
        __syncthreads();
        for (int i = tid; i < CH * 64; i += NTHR) {
            int m = i >> 6, kq = i & 63;
            int b = Sidx[m];
            float4 v = make_float4(0.f, 0.f, 0.f, 0.f);
            if (b >= 0) v = ((const float4*)(vin + (size_t)b * Hn))[kq];
            *(float4*)(Hs + m * Hn + (kq << 2)) = v;
        }
        __syncthreads();

        unsigned long long accA[16], accB[16];
#pragma unroll
        for (int m = 0; m < 16; m++) { accA[m] = 0ull; accB[m] = 0ull; }

#pragma unroll 2
        for (int k = 0; k < Hn; k += 4) {
            ulonglong2 wv = *(const ulonglong2*)(wrow + k);   // lane-distinct LDS.128
#pragma unroll
            for (int m = 0; m < 16; m++) {
                ulonglong2 hv = *(const ulonglong2*)(hbase + m * Hn + k);  // broadcast
                ffma2(accA[m], wv.x, hv.x);
                ffma2(accB[m], wv.y, hv.y);
            }
        }

        int rr = row0 + rloc;
#pragma unroll
        for (int m = 0; m < 16; m++) {
            int slot = half * 16 + m;
            if (slot < mchunk) {
                int b = Sidx[slot];
                float2 a = upk(accA[m]);
                float2 c = upk(accB[m]);
                float s = (a.x + a.y) + (c.x + c.y);
                if (!STEP || rr < Gn) {
                    oa[(size_t)b * Gn + rr] = s + bmain[camidx * Gn + rr];
                } else {
                    int o = rr - Gn;
                    float v = s + bcp[camidx * On + o];
                    dout[((size_t)b * On + o) * Tn + (t - 1)] = sigmoidf(v);
                }
            }
        }
    }
}

extern "C" void kernel_launch(void* const* d_in, const int* in_sizes, int n_in,
                              void* d_out, int out_size) {
    const float* x    = (const float*)d_in[0];
    const int*   cam  = (const int*)d_in[1];
    const float* W_ih = (const float*)d_in[2];
    const float* W_hh = (const float*)d_in[3];
    const float* b_ih = (const float*)d_in[4];
    const float* b_hh = (const float*)d_in[5];
    const float* Wc   = (const float*)d_in[6];
    const float* bc   = (const float*)d_in[7];
    float* out = (float*)d_out;

    size_t smem_gi = (size_t)128 * WS_STR * 4 + (size_t)CH * Hn * 4 + CH * sizeof(int);
    size_t smem_st = (size_t)160 * WS_STR * 4 + (size_t)CH * Hn * 4 + CH * sizeof(int);
    cudaFuncSetAttribute(gemm_tile<128, false>,
                         cudaFuncAttributeMaxDynamicSharedMemorySize, (int)smem_gi);
    cudaFuncSetAttribute(gemm_tile<160, true>,
                         cudaFuncAttributeMaxDynamicSharedMemorySize, (int)smem_st);

    // 1) group samples by camera
    group_kernel<<<1, Bn>>>(cam);
    // 2) gi = x @ W_ih^T + b_ih  (once; x is constant across timesteps)
    gemm_tile<128, false><<<Cn * 6, 256, smem_gi>>>(W_ih, nullptr, b_ih, nullptr,
                                                    x, nullptr, 0);
    // 3) h0 = 0, gh0 = b_hh
    init_kernel<<<Bn, Hn>>>(cam, b_hh);

    // 4) recurrence: at step t, GRU produces h_t from gh_{t-1}; the fused GEMM
    //    on h_t produces gh_t (for next GRU) and out_{t-1} = sigmoid(h_t@Wc+bc).
    for (int t = 1; t <= Tn; t++) {
        gru_kernel<<<Bn, Hn>>>();
        gemm_tile<160, true><<<Cn * 8, 320, smem_st>>>(W_hh, Wc, b_hh, bc,
                                                       nullptr, out, t);
    }
}

// round 5
// speedup vs baseline: 2.1164x; 2.1164x over previous
#include <cuda_runtime.h>
#include <cuda_bf16.h>
#include <cstdint>
#include <math.h>

// ---------------- problem constants ----------------
constexpr int Bn = 1024, Hn = 256, Gn = 768, On = 512, Tn = 60, Cn = 15;

// ---------------- device scratch (static, allocation-free) ----------------
// Weights, hi/lo split, per camera row-major [row][512]: k 0..255 = hi, 256..511 = lo
__device__ __align__(1024) __nv_bfloat16 g_W [ (size_t)Cn * 1280 * 512 ]; // W_hh rows 0-767, Wc rows 768-1279
__device__ __align__(1024) __nv_bfloat16 g_Wi[ (size_t)Cn * 768 * 512 ];  // W_ih
// Activations, per camera [slot 128][512]: hi | lo  (unused slots stay zero)
__device__ __align__(1024) __nv_bfloat16 g_A [ (size_t)Cn * 128 * 512 ];  // from h_t
__device__ __align__(1024) __nv_bfloat16 g_Ax[ (size_t)Cn * 128 * 512 ];  // from x
__device__ float g_gi[Bn * Gn];
__device__ float g_gh[Bn * Gn];
__device__ float g_h [Bn * Hn];
__device__ float g_outT[(size_t)Tn * Bn * On];   // [T][B][O] staging
__device__ int g_cnt[Cn], g_off[Cn], g_list[Bn], g_slot[Bn];

// ---------------- PTX helpers (sm_80-compatible only) ----------------
__device__ __forceinline__ uint32_t smem_u32(const void* p) {
    uint32_t a;
    asm("{ .reg .u64 t; cvta.to.shared.u64 t, %1; cvt.u32.u64 %0, t; }" : "=r"(a) : "l"(p));
    return a;
}
__device__ __forceinline__ void ldsm4(uint32_t& r0, uint32_t& r1, uint32_t& r2, uint32_t& r3,
                                      uint32_t addr) {
    asm volatile("ldmatrix.sync.aligned.m8n8.x4.shared.b16 {%0,%1,%2,%3}, [%4];"
                 : "=r"(r0), "=r"(r1), "=r"(r2), "=r"(r3) : "r"(addr));
}
__device__ __forceinline__ void mma16816(float* d, const uint32_t* a, const uint32_t* b) {
    asm volatile("mma.sync.aligned.m16n8k16.row.col.f32.bf16.bf16.f32 "
                 "{%0,%1,%2,%3}, {%4,%5,%6,%7}, {%8,%9}, {%0,%1,%2,%3};"
                 : "+f"(d[0]), "+f"(d[1]), "+f"(d[2]), "+f"(d[3])
                 : "r"(a[0]), "r"(a[1]), "r"(a[2]), "r"(a[3]), "r"(b[0]), "r"(b[1]));
}
__device__ __forceinline__ void cp_async16(uint32_t dst, const void* src) {
    asm volatile("cp.async.cg.shared.global [%0], [%1], 16;" :: "r"(dst), "l"(src));
}
#define CP_COMMIT() asm volatile("cp.async.commit_group;" ::: "memory")
#define CP_WAIT1()  asm volatile("cp.async.wait_group 1;" ::: "memory")
#define CP_WAIT0()  asm volatile("cp.async.wait_group 0;" ::: "memory")

__device__ __forceinline__ uint32_t swz(uint32_t x) { return x ^ ((x >> 3) & 0x70); }
__device__ __forceinline__ float sigmoidf(float x) { return 1.0f / (1.0f + expf(-x)); }
__device__ __forceinline__ uint32_t pack_bf2(float a, float b) {
    __nv_bfloat162 t = {__float2bfloat16(a), __float2bfloat16(b)};
    return *(uint32_t*)&t;
}

// ---------------- grouping ----------------
__global__ void group_kernel(const int* __restrict__ cam) {
    __shared__ int cnt[Cn], off[Cn], cur[Cn];
    int tid = threadIdx.x;
    if (tid < Cn) { cnt[tid] = 0; cur[tid] = 0; }
    __syncthreads();
    int c = cam[tid];
    atomicAdd(&cnt[c], 1);
    __syncthreads();
    if (tid == 0) { int s = 0; for (int i = 0; i < Cn; i++) { off[i] = s; s += cnt[i]; } }
    __syncthreads();
    if (tid < Cn) { g_cnt[tid] = cnt[tid]; g_off[tid] = off[tid]; }
    int p = atomicAdd(&cur[c], 1);
    g_list[off[c] + p] = tid;
    g_slot[tid] = p;
}

// ---------------- weight hi/lo split ----------------
// rows per cam: 0-767 W_hh -> g_W, 768-1279 Wc -> g_W, 1280-2047 W_ih -> g_Wi
__global__ void prep_w_kernel(const float* __restrict__ W_hh, const float* __restrict__ Wc,
                              const float* __restrict__ W_ih) {
    int row = blockIdx.x & 2047;
    int c   = blockIdx.x >> 11;
    const float* src;
    __nv_bfloat16* dst;
    if (row < 768) {
        src = W_hh + ((size_t)c * Gn + row) * Hn;
        dst = g_W + ((size_t)c * 1280 + row) * 512;
    } else if (row < 1280) {
        src = Wc + ((size_t)c * On + (row - 768)) * Hn;
        dst = g_W + ((size_t)c * 1280 + row) * 512;
    } else {
        src = W_ih + ((size_t)c * Gn + (row - 1280)) * Hn;
        dst = g_Wi + ((size_t)c * 768 + (row - 1280)) * 512;
    }
    int k0 = threadIdx.x * 2;
    float2 v = *(const float2*)(src + k0);
    float h0 = __bfloat162float(__float2bfloat16(v.x));
    float h1 = __bfloat162float(__float2bfloat16(v.y));
    *(uint32_t*)(dst + k0)       = pack_bf2(v.x, v.y);          // hi
    *(uint32_t*)(dst + 256 + k0) = pack_bf2(v.x - h0, v.y - h1); // lo
}

// ---------------- activation hi/lo split into A tiles ----------------
__device__ __forceinline__ void write_A2(__nv_bfloat16* Abase, int c, int slot,
                                         int k0, float v0, float v1) {
    __nv_bfloat16* row = Abase + ((size_t)c * 128 + slot) * 512;
    float h0 = __bfloat162float(__float2bfloat16(v0));
    float h1 = __bfloat162float(__float2bfloat16(v1));
    *(uint32_t*)(row + k0)       = pack_bf2(v0, v1);
    *(uint32_t*)(row + 256 + k0) = pack_bf2(v0 - h0, v1 - h1);
}

__global__ void build_ax_kernel(const float* __restrict__ x, const int* __restrict__ cam) {
    int b = blockIdx.x, j0 = threadIdx.x * 2;
    float2 v = *(const float2*)(x + (size_t)b * Hn + j0);
    write_A2(g_Ax, cam[b], g_slot[b], j0, v.x, v.y);
}

__global__ void init_kernel() {
    int b = blockIdx.x, j = threadIdx.x;
    g_h[b * Hn + j] = 0.0f;
    g_gh[b * Gn + j] = 0.0f;
    g_gh[b * Gn + 256 + j] = 0.0f;
    g_gh[b * Gn + 512 + j] = 0.0f;
}

// ---------------- GRU elementwise + A(h) build ----------------
__global__ void gru_kernel(const int* __restrict__ cam,
                           const float* __restrict__ b_ih, const float* __restrict__ b_hh) {
    int b = blockIdx.x, j0 = threadIdx.x * 2;
    int c = cam[b], slot = g_slot[b];
    const float* gi = g_gi + (size_t)b * Gn;
    const float* gh = g_gh + (size_t)b * Gn;
    const float* bi = b_ih + (size_t)c * Gn;
    const float* bh = b_hh + (size_t)c * Gn;
    float2 gir = *(const float2*)(gi + j0),       ghr = *(const float2*)(gh + j0);
    float2 giz = *(const float2*)(gi + 256 + j0), ghz = *(const float2*)(gh + 256 + j0);
    float2 gin = *(const float2*)(gi + 512 + j0), ghn = *(const float2*)(gh + 512 + j0);
    float2 bir = *(const float2*)(bi + j0),       bhr = *(const float2*)(bh + j0);
    float2 biz = *(const float2*)(bi + 256 + j0), bhz = *(const float2*)(bh + 256 + j0);
    float2 bin = *(const float2*)(bi + 512 + j0), bhn = *(const float2*)(bh + 512 + j0);
    float2 h = *(const float2*)(g_h + (size_t)b * Hn + j0);
    float r0 = sigmoidf(gir.x + bir.x + ghr.x + bhr.x);
    float r1 = sigmoidf(gir.y + bir.y + ghr.y + bhr.y);
    float z0 = sigmoidf(giz.x + biz.x + ghz.x + bhz.x);
    float z1 = sigmoidf(giz.y + biz.y + ghz.y + bhz.y);
    float n0 = tanhf(gin.x + bin.x + r0 * (ghn.x + bhn.x));
    float n1 = tanhf(gin.y + bin.y + r1 * (ghn.y + bhn.y));
    float hn0 = (1.0f - z0) * n0 + z0 * h.x;
    float hn1 = (1.0f - z1) * n1 + z1 * h.y;
    *(float2*)(g_h + (size_t)b * Hn + j0) = make_float2(hn0, hn1);
    write_A2(g_A, c, slot, j0, hn0, hn1);
}

// ---------------- mma.sync GEMM ----------------
// 3-term bf16 hi/lo: K' = 768 = 12 chunks of 64.
//   region 0 (cc 0-3):  A=hi, B=W_hi    region 1 (cc 4-7): A=lo, B=W_hi
//   region 2 (cc 8-11): A=hi, B=W_lo
__device__ __forceinline__ int aoff_f(int cc) { return (((cc >> 2) == 1) ? 256 : 0) + (cc & 3) * 64; }
__device__ __forceinline__ int boff_f(int cc) { return (((cc >> 2) == 2) ? 256 : 0) + (cc & 3) * 64; }

// load 128 rows x 64 bf16 (row stride 512) at bf16-col offset koff, into swizzled 16KB tile
__device__ __forceinline__ void load_tile(uint32_t sbase, const __nv_bfloat16* src,
                                          int koff, int tid) {
#pragma unroll
    for (int i = 0; i < 8; i++) {
        int idx = i * 128 + tid;              // 0..1023
        int row = idx >> 3, c16 = idx & 7;
        cp_async16(sbase + swz((uint32_t)(row * 128 + c16 * 16)),
                   src + (size_t)row * 512 + koff + c16 * 8);
    }
}

constexpr int SMEM_MMA = 65536 + 512;  // 2 stages x (16KB A + 16KB B) + Slist

template <bool GI>
__global__ void __launch_bounds__(128)
mma_kernel(const float* __restrict__ bc, int t) {
    extern __shared__ __align__(1024) unsigned char smem[];
    uint32_t sb = smem_u32(smem);
    constexpr int NT = GI ? 6 : 10;
    constexpr int NROWS = GI ? 768 : 1280;
    int tid = threadIdx.x;
    int ci = blockIdx.x / NT, nt = blockIdx.x % NT;
    int* Slist = (int*)(smem + 65536);
    Slist[tid] = (tid < g_cnt[ci]) ? g_list[g_off[ci] + tid] : -1;

    const __nv_bfloat16* Abase = (GI ? g_Ax : g_A) + (size_t)ci * 128 * 512;
    const __nv_bfloat16* Wbase = (GI ? g_Wi : g_W) + ((size_t)ci * NROWS + nt * 128) * 512;

    load_tile(sb, Abase, aoff_f(0), tid);
    load_tile(sb + 16384, Wbase, boff_f(0), tid);
    CP_COMMIT();

    int lane = tid & 31, wid = tid >> 5;
    int warpM = wid & 1, warpN = wid >> 1;       // 2 x 2 warps, 64x64 tiles
    int arow = lane & 15, khalf = (lane >> 4) << 3;

    float acc[4][8][4];
#pragma unroll
    for (int mb = 0; mb < 4; mb++)
#pragma unroll
        for (int nb = 0; nb < 8; nb++)
#pragma unroll
            for (int q = 0; q < 4; q++) acc[mb][nb][q] = 0.0f;

    for (int cc = 0; cc < 12; cc++) {
        int st = cc & 1;
        if (cc < 11) {
            int s1 = st ^ 1;
            load_tile(sb + s1 * 32768, Abase, aoff_f(cc + 1), tid);
            load_tile(sb + s1 * 32768 + 16384, Wbase, boff_f(cc + 1), tid);
            CP_COMMIT();
            CP_WAIT1();
        } else {
            CP_WAIT0();
        }
        __syncthreads();
        uint32_t As = sb + st * 32768, Bs = As + 16384;
#pragma unroll
        for (int kc = 0; kc < 4; kc++) {
            int kb = (kc << 4) + khalf;
            uint32_t a[4][4];
#pragma unroll
            for (int mb = 0; mb < 4; mb++)
                ldsm4(a[mb][0], a[mb][1], a[mb][2], a[mb][3],
                      As + swz((uint32_t)((((warpM << 6) + (mb << 4) + arow) << 7) + (kb << 1))));
            uint32_t bq[8][2];
#pragma unroll
            for (int np = 0; np < 4; np++) {
                uint32_t r0, r1, r2, r3;
                ldsm4(r0, r1, r2, r3,
                      Bs + swz((uint32_t)((((warpN << 6) + (np << 4) + arow) << 7) + (kb << 1))));
                bq[np * 2][0] = r0; bq[np * 2 + 1][0] = r1;
                bq[np * 2][1] = r2; bq[np * 2 + 1][1] = r3;
            }
#pragma unroll
            for (int mb = 0; mb < 4; mb++)
#pragma unroll
                for (int nb = 0; nb < 8; nb++)
                    mma16816(acc[mb][nb], a[mb], bq[nb]);
        }
        __syncthreads();
    }

    // epilogue: thread holds D rows {g, g+8}, cols {2tg, 2tg+1} per fragment
    int g = lane >> 2, tg = lane & 3;
#pragma unroll
    for (int mb = 0; mb < 4; mb++) {
        int m0 = (warpM << 6) + (mb << 4) + g;
        int b0 = Slist[m0], b1 = Slist[m0 + 8];
#pragma unroll
        for (int nb = 0; nb < 8; nb++) {
            float* d = acc[mb][nb];
            int n = nt * 128 + (warpN << 6) + (nb << 3) + (tg << 1);
            if (GI) {
                if (b0 >= 0) *(float2*)(g_gi + (size_t)b0 * Gn + n) = make_float2(d[0], d[1]);
                if (b1 >= 0) *(float2*)(g_gi + (size_t)b1 * Gn + n) = make_float2(d[2], d[3]);
            } else if (n < Gn) {
                if (b0 >= 0) *(float2*)(g_gh + (size_t)b0 * Gn + n) = make_float2(d[0], d[1]);
                if (b1 >= 0) *(float2*)(g_gh + (size_t)b1 * Gn + n) = make_float2(d[2], d[3]);
            } else {
                int o = n - Gn;
                float2 bb = *(const float2*)(bc + (size_t)ci * On + o);
                if (b0 >= 0)
                    *(float2*)(g_outT + ((size_t)(t - 1) * Bn + b0) * On + o) =
                        make_float2(sigmoidf(d[0] + bb.x), sigmoidf(d[1] + bb.y));
                if (b1 >= 0)
                    *(float2*)(g_outT + ((size_t)(t - 1) * Bn + b1) * On + o) =
                        make_float2(sigmoidf(d[2] + bb.x), sigmoidf(d[3] + bb.y));
            }
        }
    }
}

// ---------------- final transpose: [T][B][O] -> [B][O][T] ----------------
__global__ void transpose_kernel(float* __restrict__ dout) {
    __shared__ float s[32 * 61];
    int b = blockIdx.y, o0 = blockIdx.x * 32, tid = threadIdx.x;
    for (int idx = tid; idx < 32 * Tn; idx += 256) {
        int t = idx >> 5, oi = idx & 31;
        s[oi * 61 + t] = g_outT[((size_t)t * Bn + b) * On + o0 + oi];
    }
    __syncthreads();
    for (int idx = tid; idx < 32 * Tn; idx += 256) {
        int oi = idx / Tn, t = idx % Tn;
        dout[((size_t)b * On + o0 + oi) * Tn + t] = s[oi * 61 + t];
    }
}

// ---------------- launch ----------------
extern "C" void kernel_launch(void* const* d_in, const int* in_sizes, int n_in,
                              void* d_out, int out_size) {
    const float* x    = (const float*)d_in[0];
    const int*   cam  = (const int*)d_in[1];
    const float* W_ih = (const float*)d_in[2];
    const float* W_hh = (const float*)d_in[3];
    const float* b_ih = (const float*)d_in[4];
    const float* b_hh = (const float*)d_in[5];
    const float* Wc   = (const float*)d_in[6];
    const float* bc   = (const float*)d_in[7];
    float* out = (float*)d_out;

    cudaFuncSetAttribute(mma_kernel<true>,
                         cudaFuncAttributeMaxDynamicSharedMemorySize, SMEM_MMA);
    cudaFuncSetAttribute(mma_kernel<false>,
                         cudaFuncAttributeMaxDynamicSharedMemorySize, SMEM_MMA);

    group_kernel<<<1, Bn>>>(cam);
    prep_w_kernel<<<Cn * 2048, 128>>>(W_hh, Wc, W_ih);
    build_ax_kernel<<<Bn, 128>>>(x, cam);
    init_kernel<<<Bn, 256>>>();
    mma_kernel<true><<<Cn * 6, 128, SMEM_MMA>>>(bc, 0);     // gi = x @ W_ih^T (raw)

    for (int t = 1; t <= Tn; t++) {
        gru_kernel<<<Bn, 128>>>(cam, b_ih, b_hh);           // h_t + A(h_t)
        mma_kernel<false><<<Cn * 10, 128, SMEM_MMA>>>(bc, t); // gh_t + out_{t-1}
    }
    transpose_kernel<<<dim3(On / 32, Bn), 256>>>(out);
}

// round 6
// speedup vs baseline: 2.2161x; 1.0471x over previous
#include <cuda_runtime.h>
#include <cuda_bf16.h>
#include <cstdint>
#include <math.h>

// ---------------- problem constants ----------------
constexpr int Bn = 1024, Hn = 256, Gn = 768, On = 512, Tn = 60, Cn = 15;
constexpr int NCTA = 120;               // 15 cams x 8 N-tiles (160 rows each)

// ---------------- device scratch (static, allocation-free) ----------------
__device__ __align__(1024) __nv_bfloat16 g_W [ (size_t)Cn * 1280 * 512 ]; // W_hh rows 0-767, Wc 768-1279; [row][hi256|lo256]
__device__ __align__(1024) __nv_bfloat16 g_Wi[ (size_t)Cn * 768 * 512 ];  // W_ih split
__device__ __align__(1024) __nv_bfloat16 g_A [ (size_t)Cn * 128 * 512 ];  // A(h): [slot][hi|lo] (zero beyond cnt)
__device__ __align__(1024) __nv_bfloat16 g_Ax[ (size_t)Cn * 128 * 512 ];  // A(x)
__device__ float g_gi[Bn * Gn];          // x@W_ih^T + b_ih
__device__ float g_gh[Bn * Gn];          // h@W_hh^T + b_hh
__device__ float g_h [Bn * Hn];
__device__ float g_outT[(size_t)Tn * Bn * On];   // [T][B][O] staging
__device__ int g_cnt[Cn], g_off[Cn], g_list[Bn], g_slot[Bn];
__device__ unsigned g_ticket;            // monotonic grid-barrier counter

// ---------------- PTX helpers (family-agnostic sm_80+ only) ----------------
__device__ __forceinline__ uint32_t smem_u32(const void* p) {
    uint32_t a;
    asm("{ .reg .u64 t; cvta.to.shared.u64 t, %1; cvt.u32.u64 %0, t; }" : "=r"(a) : "l"(p));
    return a;
}
__device__ __forceinline__ void ldsm4(uint32_t& r0, uint32_t& r1, uint32_t& r2, uint32_t& r3,
                                      uint32_t addr) {
    asm volatile("ldmatrix.sync.aligned.m8n8.x4.shared.b16 {%0,%1,%2,%3}, [%4];"
                 : "=r"(r0), "=r"(r1), "=r"(r2), "=r"(r3) : "r"(addr));
}
__device__ __forceinline__ void mma16816(float* d, const uint32_t* a, const uint32_t* b) {
    asm volatile("mma.sync.aligned.m16n8k16.row.col.f32.bf16.bf16.f32 "
                 "{%0,%1,%2,%3}, {%4,%5,%6,%7}, {%8,%9}, {%0,%1,%2,%3};"
                 : "+f"(d[0]), "+f"(d[1]), "+f"(d[2]), "+f"(d[3])
                 : "r"(a[0]), "r"(a[1]), "r"(a[2]), "r"(a[3]), "r"(b[0]), "r"(b[1]));
}
__device__ __forceinline__ void cp_async16(uint32_t dst, const void* src) {
    asm volatile("cp.async.cg.shared.global [%0], [%1], 16;" :: "r"(dst), "l"(src));
}
#define CP_COMMIT() asm volatile("cp.async.commit_group;" ::: "memory")
#define CP_WAIT1()  asm volatile("cp.async.wait_group 1;" ::: "memory")
#define CP_WAIT0()  asm volatile("cp.async.wait_group 0;" ::: "memory")

__device__ __forceinline__ uint32_t swz(uint32_t x) { return x ^ ((x >> 3) & 0x70); }
__device__ __forceinline__ float sigmoidf(float x) { return 1.0f / (1.0f + expf(-x)); }
__device__ __forceinline__ uint32_t pack_bf2(float a, float b) {
    __nv_bfloat162 t = {__float2bfloat16(a), __float2bfloat16(b)};
    return *(uint32_t*)&t;
}

// grid-wide barrier: monotonic ticket counter (no reset race; replay-safe).
__device__ __forceinline__ void grid_barrier() {
    __threadfence();                       // all threads: release prior stores
    __syncthreads();
    if (threadIdx.x == 0) {
        unsigned t = atomicAdd(&g_ticket, 1u);
        unsigned need = (t / NCTA + 1u) * NCTA;
        while (*(volatile unsigned*)&g_ticket < need) __nanosleep(32);
    }
    __syncthreads();
}

// ---------------- grouping ----------------
__global__ void group_kernel(const int* __restrict__ cam) {
    __shared__ int cnt[Cn], off[Cn], cur[Cn];
    int tid = threadIdx.x;
    if (tid < Cn) { cnt[tid] = 0; cur[tid] = 0; }
    __syncthreads();
    int c = cam[tid];
    atomicAdd(&cnt[c], 1);
    __syncthreads();
    if (tid == 0) { int s = 0; for (int i = 0; i < Cn; i++) { off[i] = s; s += cnt[i]; } }
    __syncthreads();
    if (tid < Cn) { g_cnt[tid] = cnt[tid]; g_off[tid] = off[tid]; }
    int p = atomicAdd(&cur[c], 1);
    g_list[off[c] + p] = tid;
    g_slot[tid] = p;
}

// ---------------- weight hi/lo split ----------------
__global__ void prep_w_kernel(const float* __restrict__ W_hh, const float* __restrict__ Wc,
                              const float* __restrict__ W_ih) {
    int row = blockIdx.x & 2047;
    int c   = blockIdx.x >> 11;
    const float* src;
    __nv_bfloat16* dst;
    if (row < 768) {
        src = W_hh + ((size_t)c * Gn + row) * Hn;
        dst = g_W + ((size_t)c * 1280 + row) * 512;
    } else if (row < 1280) {
        src = Wc + ((size_t)c * On + (row - 768)) * Hn;
        dst = g_W + ((size_t)c * 1280 + row) * 512;
    } else {
        src = W_ih + ((size_t)c * Gn + (row - 1280)) * Hn;
        dst = g_Wi + ((size_t)c * 768 + (row - 1280)) * 512;
    }
    int k0 = threadIdx.x * 2;
    float2 v = *(const float2*)(src + k0);
    float h0 = __bfloat162float(__float2bfloat16(v.x));
    float h1 = __bfloat162float(__float2bfloat16(v.y));
    *(uint32_t*)(dst + k0)       = pack_bf2(v.x, v.y);
    *(uint32_t*)(dst + 256 + k0) = pack_bf2(v.x - h0, v.y - h1);
}

// ---------------- activation hi/lo split ----------------
__device__ __forceinline__ void write_A2(__nv_bfloat16* Abase, int c, int slot,
                                         int k0, float v0, float v1) {
    __nv_bfloat16* row = Abase + ((size_t)c * 128 + slot) * 512;
    float h0 = __bfloat162float(__float2bfloat16(v0));
    float h1 = __bfloat162float(__float2bfloat16(v1));
    *(uint32_t*)(row + k0)       = pack_bf2(v0, v1);
    *(uint32_t*)(row + 256 + k0) = pack_bf2(v0 - h0, v1 - h1);
}

__global__ void build_ax_kernel(const float* __restrict__ x, const int* __restrict__ cam) {
    int b = blockIdx.x, j0 = threadIdx.x * 2;
    float2 v = *(const float2*)(x + (size_t)b * Hn + j0);
    write_A2(g_Ax, cam[b], g_slot[b], j0, v.x, v.y);
}

// h0 = 0; gh0 = b_hh (bias is folded into gh)
__global__ void init_kernel(const int* __restrict__ cam, const float* __restrict__ b_hh) {
    int b = blockIdx.x, j = threadIdx.x;
    int c = cam[b];
    g_h[b * Hn + j] = 0.0f;
    g_gh[b * Gn + j]       = b_hh[c * Gn + j];
    g_gh[b * Gn + 256 + j] = b_hh[c * Gn + 256 + j];
    g_gh[b * Gn + 512 + j] = b_hh[c * Gn + 512 + j];
}

// ---------------- gi GEMM (once): gi = x @ W_ih^T + b_ih ----------------
__device__ __forceinline__ int aoff_f(int cc) { return (((cc >> 2) == 1) ? 256 : 0) + (cc & 3) * 64; }
__device__ __forceinline__ int boff_f(int cc) { return (((cc >> 2) == 2) ? 256 : 0) + (cc & 3) * 64; }

__device__ __forceinline__ void load_tile128(uint32_t sbase, const __nv_bfloat16* src,
                                             int koff, int tid) {
#pragma unroll
    for (int i = 0; i < 8; i++) {
        int idx = i * 128 + tid;
        int row = idx >> 3, c16 = idx & 7;
        cp_async16(sbase + swz((uint32_t)(row * 128 + c16 * 16)),
                   src + (size_t)row * 512 + koff + c16 * 8);
    }
}

constexpr int SMEM_GI = 65536 + 512;

__global__ void __launch_bounds__(128)
gi_kernel(const float* __restrict__ b_ih) {
    extern __shared__ __align__(1024) unsigned char smem[];
    uint32_t sb = smem_u32(smem);
    int tid = threadIdx.x;
    int ci = blockIdx.x / 6, nt = blockIdx.x % 6;
    int* Slist = (int*)(smem + 65536);
    Slist[tid] = (tid < g_cnt[ci]) ? g_list[g_off[ci] + tid] : -1;

    const __nv_bfloat16* Abase = g_Ax + (size_t)ci * 128 * 512;
    const __nv_bfloat16* Wbase = g_Wi + ((size_t)ci * 768 + nt * 128) * 512;

    load_tile128(sb, Abase, aoff_f(0), tid);
    load_tile128(sb + 16384, Wbase, boff_f(0), tid);
    CP_COMMIT();

    int lane = tid & 31, wid = tid >> 5;
    int warpM = wid & 1, warpN = wid >> 1;
    int arow = lane & 15, khalf = (lane >> 4) << 3;

    float acc[4][8][4];
#pragma unroll
    for (int mb = 0; mb < 4; mb++)
#pragma unroll
        for (int nb = 0; nb < 8; nb++)
#pragma unroll
            for (int q = 0; q < 4; q++) acc[mb][nb][q] = 0.0f;

    for (int cc = 0; cc < 12; cc++) {
        int st = cc & 1;
        if (cc < 11) {
            int s1 = st ^ 1;
            load_tile128(sb + s1 * 32768, Abase, aoff_f(cc + 1), tid);
            load_tile128(sb + s1 * 32768 + 16384, Wbase, boff_f(cc + 1), tid);
            CP_COMMIT();
            CP_WAIT1();
        } else CP_WAIT0();
        __syncthreads();
        uint32_t As = sb + st * 32768, Bs = As + 16384;
#pragma unroll
        for (int kc = 0; kc < 4; kc++) {
            int kb = (kc << 4) + khalf;
            uint32_t a[4][4];
#pragma unroll
            for (int mb = 0; mb < 4; mb++)
                ldsm4(a[mb][0], a[mb][1], a[mb][2], a[mb][3],
                      As + swz((uint32_t)((((warpM << 6) + (mb << 4) + arow) << 7) + (kb << 1))));
            uint32_t bq[8][2];
#pragma unroll
            for (int np = 0; np < 4; np++) {
                uint32_t r0, r1, r2, r3;
                ldsm4(r0, r1, r2, r3,
                      Bs + swz((uint32_t)((((warpN << 6) + (np << 4) + arow) << 7) + (kb << 1))));
                bq[np * 2][0] = r0; bq[np * 2 + 1][0] = r1;
                bq[np * 2][1] = r2; bq[np * 2 + 1][1] = r3;
            }
#pragma unroll
            for (int mb = 0; mb < 4; mb++)
#pragma unroll
                for (int nb = 0; nb < 8; nb++)
                    mma16816(acc[mb][nb], a[mb], bq[nb]);
        }
        __syncthreads();
    }

    int g = lane >> 2, tg = lane & 3;
#pragma unroll
    for (int mb = 0; mb < 4; mb++) {
        int m0 = (warpM << 6) + (mb << 4) + g;
        int b0 = Slist[m0], b1 = Slist[m0 + 8];
#pragma unroll
        for (int nb = 0; nb < 8; nb++) {
            float* d = acc[mb][nb];
            int n = nt * 128 + (warpN << 6) + (nb << 3) + (tg << 1);
            float2 bb = *(const float2*)(b_ih + (size_t)ci * Gn + n);
            if (b0 >= 0) *(float2*)(g_gi + (size_t)b0 * Gn + n) = make_float2(d[0] + bb.x, d[1] + bb.y);
            if (b1 >= 0) *(float2*)(g_gi + (size_t)b1 * Gn + n) = make_float2(d[2] + bb.x, d[3] + bb.y);
        }
    }
}

// ---------------- persistent recurrence kernel ----------------
// 120 CTAs (ci = blk/8, nt = blk%8), 256 threads. B tile (160 rows x [hi|lo])
// resident in SMEM; A streamed per k-chunk (hi+lo), double-buffered.
constexpr uint32_t SB_B  = 0;        // 8 sub-tiles x 20480 B = 160 KB
constexpr uint32_t SB_A  = 163840;   // 2 stages x (16KB Ahi + 16KB Alo) = 64 KB
constexpr uint32_t SB_SL = 229376;   // 128 ints
constexpr int SMEM_P = 229376 + 512;

__device__ __forceinline__ void load_A_chunk(uint32_t dsthi, uint32_t dstlo,
                                             const __nv_bfloat16* Abase, int c, int tid) {
#pragma unroll
    for (int i = 0; i < 4; i++) {
        int idx = i * 256 + tid;          // 0..1023
        int row = idx >> 3, c16 = idx & 7;
        uint32_t so = swz((uint32_t)(row * 128 + c16 * 16));
        const __nv_bfloat16* rp = Abase + (size_t)row * 512 + c * 64 + c16 * 8;
        cp_async16(dsthi + so, rp);
        cp_async16(dstlo + so, rp + 256);
    }
}

__global__ void __launch_bounds__(256, 1)
persist_kernel(const float* __restrict__ b_hh, const float* __restrict__ bc) {
    extern __shared__ __align__(1024) unsigned char smem[];
    uint32_t sb = smem_u32(smem);
    int tid = threadIdx.x, lane = tid & 31, wid = tid >> 5;
    int ci = blockIdx.x >> 3, nt = blockIdx.x & 7;
    int* Slist = (int*)(smem + SB_SL);
    int cnt = g_cnt[ci];
    if (tid < 128) Slist[tid] = (tid < cnt) ? g_list[g_off[ci] + tid] : -1;

    // ---- prologue: resident B tile (Whi c0-3, Wlo c0-3; 160 rows each) ----
    const __nv_bfloat16* Wb = g_W + ((size_t)ci * 1280 + nt * 160) * 512;
    for (int i = tid; i < 10240; i += 256) {
        int tile = i / 1280, rem = i - tile * 1280;
        int row = rem >> 3, c16 = rem & 7;
        int col = (tile < 4 ? tile * 64 : 256 + (tile - 4) * 64) + c16 * 8;
        cp_async16(sb + SB_B + tile * 20480 + swz((uint32_t)(row * 128 + c16 * 16)),
                   Wb + (size_t)row * 512 + col);
    }
    CP_COMMIT(); CP_WAIT0();
    __syncthreads();

    const __nv_bfloat16* Abase = g_A + (size_t)ci * 128 * 512;
    int warpM = wid & 3, warpN = wid >> 2;       // 4 M-warps x 2 N-warps (32 x 80)
    int arow = lane & 15, khalf = (lane >> 4) << 3;
    int g = lane >> 2, tg = lane & 3;
    int gslot = nt * 16 + (tid >> 4);            // gru: 16 slots per CTA
    int gj0 = (tid & 15) * 2;

    for (int t = 1; t <= Tn; t++) {
        // ---- GRU phase: h_t from gh_{t-1} (bias folded), gi (bias folded) ----
        {
            int b = Slist[gslot];
            if (b >= 0) {
                const float* gi = g_gi + (size_t)b * Gn;
                const float* gh = g_gh + (size_t)b * Gn;
                float* hp = g_h + (size_t)b * Hn;
#pragma unroll
                for (int jj = 0; jj < 8; jj++) {
                    int j = gj0 + jj * 32;
                    float2 gr = __ldcg((const float2*)(gh + j));
                    float2 gz = __ldcg((const float2*)(gh + 256 + j));
                    float2 gn = __ldcg((const float2*)(gh + 512 + j));
                    float2 ir = *(const float2*)(gi + j);
                    float2 iz = *(const float2*)(gi + 256 + j);
                    float2 in_ = *(const float2*)(gi + 512 + j);
                    float2 h = *(const float2*)(hp + j);
                    float r0 = sigmoidf(ir.x + gr.x), r1 = sigmoidf(ir.y + gr.y);
                    float z0 = sigmoidf(iz.x + gz.x), z1 = sigmoidf(iz.y + gz.y);
                    float n0 = tanhf(in_.x + r0 * gn.x), n1 = tanhf(in_.y + r1 * gn.y);
                    float h0 = (1.0f - z0) * n0 + z0 * h.x;
                    float h1 = (1.0f - z1) * n1 + z1 * h.y;
                    *(float2*)(hp + j) = make_float2(h0, h1);
                    write_A2(g_A, ci, gslot, j, h0, h1);
                }
            }
        }
        grid_barrier();   // A(h_t) visible to all CTAs of this camera

        // ---- MMA phase: [gh_t ; out_{t-1}] rows nt*160..+160 ----
        float acc[2][10][4];
#pragma unroll
        for (int mb = 0; mb < 2; mb++)
#pragma unroll
            for (int nb = 0; nb < 10; nb++)
#pragma unroll
                for (int q = 0; q < 4; q++) acc[mb][nb][q] = 0.0f;

        load_A_chunk(sb + SB_A, sb + SB_A + 16384, Abase, 0, tid);
        CP_COMMIT();
        for (int c = 0; c < 4; c++) {
            int st = c & 1;
            if (c < 3) {
                load_A_chunk(sb + SB_A + (st ^ 1) * 32768,
                             sb + SB_A + (st ^ 1) * 32768 + 16384, Abase, c + 1, tid);
                CP_COMMIT(); CP_WAIT1();
            } else CP_WAIT0();
            __syncthreads();
            uint32_t Ahi = sb + SB_A + st * 32768, Alo = Ahi + 16384;
            uint32_t Whi = sb + SB_B + c * 20480, Wlo = Whi + 4 * 20480;
#pragma unroll
            for (int kc = 0; kc < 4; kc++) {
                int kb = (kc << 4) + khalf;
                uint32_t ah[2][4], al[2][4];
#pragma unroll
                for (int mb = 0; mb < 2; mb++) {
                    if (warpM * 32 + mb * 16 < cnt) {
                        uint32_t ro = (uint32_t)(((warpM * 32 + mb * 16 + arow) << 7) + (kb << 1));
                        ldsm4(ah[mb][0], ah[mb][1], ah[mb][2], ah[mb][3], Ahi + swz(ro));
                        ldsm4(al[mb][0], al[mb][1], al[mb][2], al[mb][3], Alo + swz(ro));
                    }
                }
                uint32_t bh_[10][2], bl_[10][2];
#pragma unroll
                for (int np = 0; np < 5; np++) {
                    uint32_t ro = (uint32_t)(((warpN * 80 + np * 16 + arow) << 7) + (kb << 1));
                    uint32_t r0, r1, r2, r3;
                    ldsm4(r0, r1, r2, r3, Whi + swz(ro));
                    bh_[np * 2][0] = r0; bh_[np * 2 + 1][0] = r1;
                    bh_[np * 2][1] = r2; bh_[np * 2 + 1][1] = r3;
                    ldsm4(r0, r1, r2, r3, Wlo + swz(ro));
                    bl_[np * 2][0] = r0; bl_[np * 2 + 1][0] = r1;
                    bl_[np * 2][1] = r2; bl_[np * 2 + 1][1] = r3;
                }
#pragma unroll
                for (int mb = 0; mb < 2; mb++) {
                    if (warpM * 32 + mb * 16 >= cnt) continue;
#pragma unroll
                    for (int nb = 0; nb < 10; nb++) {
                        mma16816(acc[mb][nb], ah[mb], bh_[nb]);   // hi*Whi
                        mma16816(acc[mb][nb], al[mb], bh_[nb]);   // lo*Whi
                        mma16816(acc[mb][nb], ah[mb], bl_[nb]);   // hi*Wlo
                    }
                }
            }
            __syncthreads();
        }

        // ---- epilogue: gh (+b_hh) raw, out rows sigmoid(+bc) ----
        int nbase = nt * 160 + warpN * 80;
#pragma unroll
        for (int mb = 0; mb < 2; mb++) {
            int m0 = warpM * 32 + mb * 16 + g;
            int b0 = (m0 < 128) ? Slist[m0] : -1;
            int b1 = (m0 + 8 < 128) ? Slist[m0 + 8] : -1;
#pragma unroll
            for (int nb = 0; nb < 10; nb++) {
                float* d = acc[mb][nb];
                int n = nbase + nb * 8 + tg * 2;
                if (n < Gn) {
                    float2 bb = *(const float2*)(b_hh + (size_t)ci * Gn + n);
                    if (b0 >= 0) *(float2*)(g_gh + (size_t)b0 * Gn + n) =
                        make_float2(d[0] + bb.x, d[1] + bb.y);
                    if (b1 >= 0) *(float2*)(g_gh + (size_t)b1 * Gn + n) =
                        make_float2(d[2] + bb.x, d[3] + bb.y);
                } else {
                    int o = n - Gn;
                    float2 bb = *(const float2*)(bc + (size_t)ci * On + o);
                    if (b0 >= 0) *(float2*)(g_outT + ((size_t)(t - 1) * Bn + b0) * On + o) =
                        make_float2(sigmoidf(d[0] + bb.x), sigmoidf(d[1] + bb.y));
                    if (b1 >= 0) *(float2*)(g_outT + ((size_t)(t - 1) * Bn + b1) * On + o) =
                        make_float2(sigmoidf(d[2] + bb.x), sigmoidf(d[3] + bb.y));
                }
            }
        }
        grid_barrier();   // gh_t visible for next step's GRU
    }
}

// ---------------- final transpose: [T][B][O] -> [B][O][T] ----------------
__global__ void transpose_kernel(float* __restrict__ dout) {
    __shared__ float s[32 * 61];
    int b = blockIdx.y, o0 = blockIdx.x * 32, tid = threadIdx.x;
    for (int idx = tid; idx < 32 * Tn; idx += 256) {
        int t = idx >> 5, oi = idx & 31;
        s[oi * 61 + t] = g_outT[((size_t)t * Bn + b) * On + o0 + oi];
    }
    __syncthreads();
    for (int idx = tid; idx < 32 * Tn; idx += 256) {
        int oi = idx / Tn, t = idx % Tn;
        dout[((size_t)b * On + o0 + oi) * Tn + t] = s[oi * 61 + t];
    }
}

// ---------------- launch ----------------
extern "C" void kernel_launch(void* const* d_in, const int* in_sizes, int n_in,
                              void* d_out, int out_size) {
    const float* x    = (const float*)d_in[0];
    const int*   cam  = (const int*)d_in[1];
    const float* W_ih = (const float*)d_in[2];
    const float* W_hh = (const float*)d_in[3];
    const float* b_ih = (const float*)d_in[4];
    const float* b_hh = (const float*)d_in[5];
    const float* Wc   = (const float*)d_in[6];
    const float* bc   = (const float*)d_in[7];
    float* out = (float*)d_out;

    cudaFuncSetAttribute(gi_kernel, cudaFuncAttributeMaxDynamicSharedMemorySize, SMEM_GI);
    cudaFuncSetAttribute(persist_kernel, cudaFuncAttributeMaxDynamicSharedMemorySize, SMEM_P);

    group_kernel<<<1, Bn>>>(cam);
    prep_w_kernel<<<Cn * 2048, 128>>>(W_hh, Wc, W_ih);
    build_ax_kernel<<<Bn, 128>>>(x, cam);
    init_kernel<<<Bn, 256>>>(cam, b_hh);
    gi_kernel<<<Cn * 6, 128, SMEM_GI>>>(b_ih);           // gi = x@W_ih^T + b_ih

    persist_kernel<<<NCTA, 256, SMEM_P>>>(b_hh, bc);     // full 60-step recurrence

    transpose_kernel<<<dim3(On / 32, Bn), 256>>>(out);
}

// round 7
// speedup vs baseline: 2.5774x; 1.1630x over previous
#include <cuda_runtime.h>
#include <cuda_bf16.h>
#include <cstdint>
#include <math.h>

// ---------------- problem constants ----------------
constexpr int Bn = 1024, Hn = 256, Gn = 768, On = 512, Tn = 60, Cn = 15;
constexpr int NCTA = 120;               // 15 clusters x 8 CTAs

// ---------------- device scratch (static, allocation-free) ----------------
__device__ __align__(1024) __nv_bfloat16 g_W [ (size_t)Cn * 1280 * 512 ]; // rows: 0-767 W_hh, 768-1279 Wc; [row][hi256|lo256]
__device__ __align__(1024) __nv_bfloat16 g_Wi[ (size_t)Cn * 768 * 512 ];  // W_ih split
__device__ __align__(1024) __nv_bfloat16 g_A [ (size_t)Cn * 128 * 512 ];  // A(h): [slot][hi|lo]
__device__ __align__(1024) __nv_bfloat16 g_Ax[ (size_t)Cn * 128 * 512 ];  // A(x)
__device__ float g_gi[Bn * Gn];
__device__ float g_gh[Bn * Gn];
__device__ float g_h [Bn * Hn];
__device__ float g_outT[(size_t)Tn * Bn * On];   // [T][B][O] staging
__device__ int g_cnt[Cn], g_off[Cn], g_list[Bn], g_slot[Bn];

// ---------------- PTX helpers (family-agnostic sm_90-portable) ----------------
__device__ __forceinline__ uint32_t smem_u32(const void* p) {
    uint32_t a;
    asm("{ .reg .u64 t; cvta.to.shared.u64 t, %1; cvt.u32.u64 %0, t; }" : "=r"(a) : "l"(p));
    return a;
}
__device__ __forceinline__ void ldsm4(uint32_t& r0, uint32_t& r1, uint32_t& r2, uint32_t& r3,
                                      uint32_t addr) {
    asm volatile("ldmatrix.sync.aligned.m8n8.x4.shared.b16 {%0,%1,%2,%3}, [%4];"
                 : "=r"(r0), "=r"(r1), "=r"(r2), "=r"(r3) : "r"(addr));
}
__device__ __forceinline__ void mma16816(float* d, const uint32_t* a, const uint32_t* b) {
    asm volatile("mma.sync.aligned.m16n8k16.row.col.f32.bf16.bf16.f32 "
                 "{%0,%1,%2,%3}, {%4,%5,%6,%7}, {%8,%9}, {%0,%1,%2,%3};"
                 : "+f"(d[0]), "+f"(d[1]), "+f"(d[2]), "+f"(d[3])
                 : "r"(a[0]), "r"(a[1]), "r"(a[2]), "r"(a[3]), "r"(b[0]), "r"(b[1]));
}
__device__ __forceinline__ void cp_async16(uint32_t dst, const void* src) {
    asm volatile("cp.async.cg.shared.global [%0], [%1], 16;" :: "r"(dst), "l"(src));
}
#define CP_COMMIT() asm volatile("cp.async.commit_group;" ::: "memory")
#define CP_WAIT1()  asm volatile("cp.async.wait_group 1;" ::: "memory")
#define CP_WAIT0()  asm volatile("cp.async.wait_group 0;" ::: "memory")
// hw cluster barrier: arrive has release, wait has acquire (cluster scope)
#define CLUSTER_ARRIVE() asm volatile("barrier.cluster.arrive.aligned;" ::: "memory")
#define CLUSTER_WAIT()   asm volatile("barrier.cluster.wait.aligned;" ::: "memory")

__device__ __forceinline__ uint32_t swz(uint32_t x) { return x ^ ((x >> 3) & 0x70); }
__device__ __forceinline__ float sigmoidf(float x) { return 1.0f / (1.0f + expf(-x)); }
__device__ __forceinline__ uint32_t pack_bf2(float a, float b) {
    __nv_bfloat162 t = {__float2bfloat16(a), __float2bfloat16(b)};
    return *(uint32_t*)&t;
}

// ---------------- grouping ----------------
__global__ void group_kernel(const int* __restrict__ cam) {
    __shared__ int cnt[Cn], off[Cn], cur[Cn];
    int tid = threadIdx.x;
    if (tid < Cn) { cnt[tid] = 0; cur[tid] = 0; }
    __syncthreads();
    int c = cam[tid];
    atomicAdd(&cnt[c], 1);
    __syncthreads();
    if (tid == 0) { int s = 0; for (int i = 0; i < Cn; i++) { off[i] = s; s += cnt[i]; } }
    __syncthreads();
    if (tid < Cn) { g_cnt[tid] = cnt[tid]; g_off[tid] = off[tid]; }
    int p = atomicAdd(&cur[c], 1);
    g_list[off[c] + p] = tid;
    g_slot[tid] = p;
}

// ---------------- weight hi/lo split ----------------
__global__ void prep_w_kernel(const float* __restrict__ W_hh, const float* __restrict__ Wc,
                              const float* __restrict__ W_ih) {
    int row = blockIdx.x & 2047;
    int c   = blockIdx.x >> 11;
    const float* src;
    __nv_bfloat16* dst;
    if (row < 768) {
        src = W_hh + ((size_t)c * Gn + row) * Hn;
        dst = g_W + ((size_t)c * 1280 + row) * 512;
    } else if (row < 1280) {
        src = Wc + ((size_t)c * On + (row - 768)) * Hn;
        dst = g_W + ((size_t)c * 1280 + row) * 512;
    } else {
        src = W_ih + ((size_t)c * Gn + (row - 1280)) * Hn;
        dst = g_Wi + ((size_t)c * 768 + (row - 1280)) * 512;
    }
    int k0 = threadIdx.x * 2;
    float2 v = *(const float2*)(src + k0);
    float h0 = __bfloat162float(__float2bfloat16(v.x));
    float h1 = __bfloat162float(__float2bfloat16(v.y));
    *(uint32_t*)(dst + k0)       = pack_bf2(v.x, v.y);
    *(uint32_t*)(dst + 256 + k0) = pack_bf2(v.x - h0, v.y - h1);
}

// ---------------- activation hi/lo split ----------------
__device__ __forceinline__ void write_A2(__nv_bfloat16* Abase, int c, int slot,
                                         int k0, float v0, float v1) {
    __nv_bfloat16* row = Abase + ((size_t)c * 128 + slot) * 512;
    float h0 = __bfloat162float(__float2bfloat16(v0));
    float h1 = __bfloat162float(__float2bfloat16(v1));
    *(uint32_t*)(row + k0)       = pack_bf2(v0, v1);
    *(uint32_t*)(row + 256 + k0) = pack_bf2(v0 - h0, v1 - h1);
}

__global__ void build_ax_kernel(const float* __restrict__ x, const int* __restrict__ cam) {
    int b = blockIdx.x, j0 = threadIdx.x * 2;
    float2 v = *(const float2*)(x + (size_t)b * Hn + j0);
    write_A2(g_Ax, cam[b], g_slot[b], j0, v.x, v.y);
}

// h0 = 0; gh0 = b_hh (bias folded into gh)
__global__ void init_kernel(const int* __restrict__ cam, const float* __restrict__ b_hh) {
    int b = blockIdx.x, j = threadIdx.x;
    int c = cam[b];
    g_h[b * Hn + j] = 0.0f;
    g_gh[b * Gn + j]       = b_hh[c * Gn + j];
    g_gh[b * Gn + 256 + j] = b_hh[c * Gn + 256 + j];
    g_gh[b * Gn + 512 + j] = b_hh[c * Gn + 512 + j];
}

// ---------------- gi GEMM (once): gi = x @ W_ih^T + b_ih ----------------
__device__ __forceinline__ int aoff_f(int cc) { return (((cc >> 2) == 1) ? 256 : 0) + (cc & 3) * 64; }
__device__ __forceinline__ int boff_f(int cc) { return (((cc >> 2) == 2) ? 256 : 0) + (cc & 3) * 64; }

__device__ __forceinline__ void load_tile128(uint32_t sbase, const __nv_bfloat16* src,
                                             int koff, int tid) {
#pragma unroll
    for (int i = 0; i < 8; i++) {
        int idx = i * 128 + tid;
        int row = idx >> 3, c16 = idx & 7;
        cp_async16(sbase + swz((uint32_t)(row * 128 + c16 * 16)),
                   src + (size_t)row * 512 + koff + c16 * 8);
    }
}

constexpr int SMEM_GI = 65536 + 512;

__global__ void __launch_bounds__(128)
gi_kernel(const float* __restrict__ b_ih) {
    extern __shared__ __align__(1024) unsigned char smem[];
    uint32_t sb = smem_u32(smem);
    int tid = threadIdx.x;
    int ci = blockIdx.x / 6, nt = blockIdx.x % 6;
    int* Slist = (int*)(smem + 65536);
    Slist[tid] = (tid < g_cnt[ci]) ? g_list[g_off[ci] + tid] : -1;

    const __nv_bfloat16* Abase = g_Ax + (size_t)ci * 128 * 512;
    const __nv_bfloat16* Wbase = g_Wi + ((size_t)ci * 768 + nt * 128) * 512;

    load_tile128(sb, Abase, aoff_f(0), tid);
    load_tile128(sb + 16384, Wbase, boff_f(0), tid);
    CP_COMMIT();

    int lane = tid & 31, wid = tid >> 5;
    int warpM = wid & 1, warpN = wid >> 1;
    int arow = lane & 15, khalf = (lane >> 4) << 3;

    float acc[4][8][4];
#pragma unroll
    for (int mb = 0; mb < 4; mb++)
#pragma unroll
        for (int nb = 0; nb < 8; nb++)
#pragma unroll
            for (int q = 0; q < 4; q++) acc[mb][nb][q] = 0.0f;

    for (int cc = 0; cc < 12; cc++) {
        int st = cc & 1;
        if (cc < 11) {
            int s1 = st ^ 1;
            load_tile128(sb + s1 * 32768, Abase, aoff_f(cc + 1), tid);
            load_tile128(sb + s1 * 32768 + 16384, Wbase, boff_f(cc + 1), tid);
            CP_COMMIT();
            CP_WAIT1();
        } else CP_WAIT0();
        __syncthreads();
        uint32_t As = sb + st * 32768, Bs = As + 16384;
#pragma unroll
        for (int kc = 0; kc < 4; kc++) {
            int kb = (kc << 4) + khalf;
            uint32_t a[4][4];
#pragma unroll
            for (int mb = 0; mb < 4; mb++)
                ldsm4(a[mb][0], a[mb][1], a[mb][2], a[mb][3],
                      As + swz((uint32_t)((((warpM << 6) + (mb << 4) + arow) << 7) + (kb << 1))));
            uint32_t bq[8][2];
#pragma unroll
            for (int np = 0; np < 4; np++) {
                uint32_t r0, r1, r2, r3;
                ldsm4(r0, r1, r2, r3,
                      Bs + swz((uint32_t)((((warpN << 6) + (np << 4) + arow) << 7) + (kb << 1))));
                bq[np * 2][0] = r0; bq[np * 2 + 1][0] = r1;
                bq[np * 2][1] = r2; bq[np * 2 + 1][1] = r3;
            }
#pragma unroll
            for (int mb = 0; mb < 4; mb++)
#pragma unroll
                for (int nb = 0; nb < 8; nb++)
                    mma16816(acc[mb][nb], a[mb], bq[nb]);
        }
        __syncthreads();
    }

    int g = lane >> 2, tg = lane & 3;
#pragma unroll
    for (int mb = 0; mb < 4; mb++) {
        int m0 = (warpM << 6) + (mb << 4) + g;
        int b0 = Slist[m0], b1 = Slist[m0 + 8];
#pragma unroll
        for (int nb = 0; nb < 8; nb++) {
            float* d = acc[mb][nb];
            int n = nt * 128 + (warpN << 6) + (nb << 3) + (tg << 1);
            float2 bb = *(const float2*)(b_ih + (size_t)ci * Gn + n);
            if (b0 >= 0) *(float2*)(g_gi + (size_t)b0 * Gn + n) = make_float2(d[0] + bb.x, d[1] + bb.y);
            if (b1 >= 0) *(float2*)(g_gi + (size_t)b1 * Gn + n) = make_float2(d[2] + bb.x, d[3] + bb.y);
        }
    }
}

// ---------------- persistent clustered recurrence kernel ----------------
// cluster = 8 CTAs = one camera. rank 0-5: gh tiles (128 rows, 3-term K'=768).
// rank 6-7: out tiles (256 rows, 1-term K=256). Weights SMEM-resident.
constexpr uint32_t SB_W  = 0;        // 128 KB resident weights
constexpr uint32_t SB_A  = 131072;   // 2 stages x 32 KB A ring
constexpr uint32_t SB_SL = 196608;   // 128 ints
constexpr int SMEM_P = 196608 + 512;

__device__ __forceinline__ void load_A2(uint32_t dsthi, uint32_t dstlo,
                                        const __nv_bfloat16* Abase, int c, int tid) {
#pragma unroll
    for (int i = 0; i < 4; i++) {
        int idx = i * 256 + tid;          // 0..1023
        int row = idx >> 3, c16 = idx & 7;
        uint32_t so = swz((uint32_t)(row * 128 + c16 * 16));
        const __nv_bfloat16* rp = Abase + (size_t)row * 512 + c * 64 + c16 * 8;
        cp_async16(dsthi + so, rp);
        cp_async16(dstlo + so, rp + 256);
    }
}
__device__ __forceinline__ void load_A1(uint32_t dsthi,
                                        const __nv_bfloat16* Abase, int c, int tid) {
#pragma unroll
    for (int i = 0; i < 4; i++) {
        int idx = i * 256 + tid;
        int row = idx >> 3, c16 = idx & 7;
        cp_async16(dsthi + swz((uint32_t)(row * 128 + c16 * 16)),
                   Abase + (size_t)row * 512 + c * 64 + c16 * 8);
    }
}

__global__ void __cluster_dims__(8, 1, 1) __launch_bounds__(256, 1)
persist_kernel(const float* __restrict__ b_hh, const float* __restrict__ bc) {
    extern __shared__ __align__(1024) unsigned char smem[];
    uint32_t sb = smem_u32(smem);
    int tid = threadIdx.x, lane = tid & 31, wid = tid >> 5;
    int ci = blockIdx.x >> 3, rank = blockIdx.x & 7;
    bool isOut = rank >= 6;
    int* Slist = (int*)(smem + SB_SL);
    int cnt = g_cnt[ci];
    if (tid < 128) Slist[tid] = (tid < cnt) ? g_list[g_off[ci] + tid] : -1;

    // ---- prologue: resident weight tile ----
    if (!isOut) {
        const __nv_bfloat16* Wb = g_W + ((size_t)ci * 1280 + rank * 128) * 512;
        for (int i = tid; i < 8192; i += 256) {      // 8 sub-tiles x 1024 vec16
            int t = i >> 10, rem = i & 1023;
            int row = rem >> 3, c16 = rem & 7;
            int col = (t < 4 ? t * 64 : 256 + (t - 4) * 64) + c16 * 8;
            cp_async16(sb + SB_W + t * 16384 + swz((uint32_t)(row * 128 + c16 * 16)),
                       Wb + (size_t)row * 512 + col);
        }
    } else {
        const __nv_bfloat16* Wb = g_W + ((size_t)ci * 1280 + 768 + (rank - 6) * 256) * 512;
        for (int i = tid; i < 8192; i += 256) {      // 4 sub-tiles x 2048 vec16
            int t = i >> 11, rem = i & 2047;
            int row = rem >> 3, c16 = rem & 7;
            int col = t * 64 + c16 * 8;
            cp_async16(sb + SB_W + t * 32768 + swz((uint32_t)(row * 128 + c16 * 16)),
                       Wb + (size_t)row * 512 + col);
        }
    }
    CP_COMMIT(); CP_WAIT0();
    __syncthreads();

    const __nv_bfloat16* Abase = g_A + (size_t)ci * 128 * 512;
    // warp layout: warpN = SMSP id -> each SMSP gets one dense-M and one sparse-M warp
    int warpN = wid & 3, warpM = wid >> 2;
    int arow = lane & 15, khalf = (lane >> 4) << 3;
    int g = lane >> 2, tg = lane & 3;
    int gslot = rank * 16 + (tid >> 4), gj0 = (tid & 15) * 2;

    for (int t = 1; t <= Tn; t++) {
        // ---- GRU phase (16 slots per CTA) ----
        {
            int b = Slist[gslot];
            if (b >= 0) {
                const float* gi = g_gi + (size_t)b * Gn;
                const float* gh = g_gh + (size_t)b * Gn;
                float* hp = g_h + (size_t)b * Hn;
#pragma unroll
                for (int jj = 0; jj < 8; jj++) {
                    int j = gj0 + jj * 32;
                    float2 gr = __ldcg((const float2*)(gh + j));
                    float2 gz = __ldcg((const float2*)(gh + 256 + j));
                    float2 gn = __ldcg((const float2*)(gh + 512 + j));
                    float2 ir = *(const float2*)(gi + j);
                    float2 iz = *(const float2*)(gi + 256 + j);
                    float2 in_ = *(const float2*)(gi + 512 + j);
                    float2 h = *(const float2*)(hp + j);
                    float r0 = sigmoidf(ir.x + gr.x), r1 = sigmoidf(ir.y + gr.y);
                    float z0 = sigmoidf(iz.x + gz.x), z1 = sigmoidf(iz.y + gz.y);
                    float n0 = tanhf(in_.x + r0 * gn.x), n1 = tanhf(in_.y + r1 * gn.y);
                    float h0 = (1.0f - z0) * n0 + z0 * h.x;
                    float h1 = (1.0f - z1) * n1 + z1 * h.y;
                    *(float2*)(hp + j) = make_float2(h0, h1);
                    write_A2(g_A, ci, gslot, j, h0, h1);
                }
            }
        }
        CLUSTER_ARRIVE(); CLUSTER_WAIT();    // A(h_t) visible in-cluster

        if (!isOut) {
            if (t < Tn) {                    // gh_60 never consumed
                float acc[4][4][4];
#pragma unroll
                for (int mb = 0; mb < 4; mb++)
#pragma unroll
                    for (int nb = 0; nb < 4; nb++)
#pragma unroll
                        for (int q = 0; q < 4; q++) acc[mb][nb][q] = 0.0f;

                load_A2(sb + SB_A, sb + SB_A + 16384, Abase, 0, tid);
                CP_COMMIT();
                for (int c = 0; c < 4; c++) {
                    int st = c & 1;
                    if (c < 3) {
                        load_A2(sb + SB_A + (st ^ 1) * 32768,
                                sb + SB_A + (st ^ 1) * 32768 + 16384, Abase, c + 1, tid);
                        CP_COMMIT(); CP_WAIT1();
                    } else CP_WAIT0();
                    __syncthreads();
                    uint32_t Ahi = sb + SB_A + st * 32768, Alo = Ahi + 16384;
                    uint32_t Whi = sb + SB_W + c * 16384, Wlo = sb + SB_W + (4 + c) * 16384;
#pragma unroll
                    for (int kc = 0; kc < 4; kc++) {
                        int kb = (kc << 4) + khalf;
                        uint32_t ah[4][4], al[4][4];
#pragma unroll
                        for (int mb = 0; mb < 4; mb++) {
                            int r0 = warpM * 64 + mb * 16;
                            if (r0 < cnt) {
                                uint32_t ro = (uint32_t)(((r0 + arow) << 7) + (kb << 1));
                                ldsm4(ah[mb][0], ah[mb][1], ah[mb][2], ah[mb][3], Ahi + swz(ro));
                                ldsm4(al[mb][0], al[mb][1], al[mb][2], al[mb][3], Alo + swz(ro));
                            }
                        }
                        uint32_t bh_[4][2], bl_[4][2];
#pragma unroll
                        for (int np = 0; np < 2; np++) {
                            uint32_t ro = (uint32_t)(((warpN * 32 + np * 16 + arow) << 7) + (kb << 1));
                            uint32_t r0, r1, r2, r3;
                            ldsm4(r0, r1, r2, r3, Whi + swz(ro));
                            bh_[np * 2][0] = r0; bh_[np * 2 + 1][0] = r1;
                            bh_[np * 2][1] = r2; bh_[np * 2 + 1][1] = r3;
                            ldsm4(r0, r1, r2, r3, Wlo + swz(ro));
                            bl_[np * 2][0] = r0; bl_[np * 2 + 1][0] = r1;
                            bl_[np * 2][1] = r2; bl_[np * 2 + 1][1] = r3;
                        }
#pragma unroll
                        for (int mb = 0; mb < 4; mb++) {
                            if (warpM * 64 + mb * 16 >= cnt) continue;
#pragma unroll
                            for (int nb = 0; nb < 4; nb++) {
                                mma16816(acc[mb][nb], ah[mb], bh_[nb]);
                                mma16816(acc[mb][nb], al[mb], bh_[nb]);
                                mma16816(acc[mb][nb], ah[mb], bl_[nb]);
                            }
                        }
                    }
                    __syncthreads();
                }
                int nbase = rank * 128 + warpN * 32;
#pragma unroll
                for (int mb = 0; mb < 4; mb++) {
                    int m0 = warpM * 64 + mb * 16 + g;
                    int b0 = Slist[m0], b1 = Slist[m0 + 8];
#pragma unroll
                    for (int nb = 0; nb < 4; nb++) {
                        float* d = acc[mb][nb];
                        int n = nbase + nb * 8 + tg * 2;
                        float2 bb = *(const float2*)(b_hh + (size_t)ci * Gn + n);
                        if (b0 >= 0) *(float2*)(g_gh + (size_t)b0 * Gn + n) =
                            make_float2(d[0] + bb.x, d[1] + bb.y);
                        if (b1 >= 0) *(float2*)(g_gh + (size_t)b1 * Gn + n) =
                            make_float2(d[2] + bb.x, d[3] + bb.y);
                    }
                }
            }
        } else {
            // out tile: 256 rows, single hi*hi term, K=256
            float acc[4][8][4];
#pragma unroll
            for (int mb = 0; mb < 4; mb++)
#pragma unroll
                for (int nb = 0; nb < 8; nb++)
#pragma unroll
                    for (int q = 0; q < 4; q++) acc[mb][nb][q] = 0.0f;

            load_A1(sb + SB_A, Abase, 0, tid);
            CP_COMMIT();
            for (int c = 0; c < 4; c++) {
                int st = c & 1;
                if (c < 3) {
                    load_A1(sb + SB_A + (st ^ 1) * 32768, Abase, c + 1, tid);
                    CP_COMMIT(); CP_WAIT1();
                } else CP_WAIT0();
                __syncthreads();
                uint32_t Ahi = sb + SB_A + st * 32768;
                uint32_t Ws = sb + SB_W + c * 32768;
#pragma unroll
                for (int kc = 0; kc < 4; kc++) {
                    int kb = (kc << 4) + khalf;
                    uint32_t ah[4][4];
#pragma unroll
                    for (int mb = 0; mb < 4; mb++) {
                        int r0 = warpM * 64 + mb * 16;
                        if (r0 < cnt)
                            ldsm4(ah[mb][0], ah[mb][1], ah[mb][2], ah[mb][3],
                                  Ahi + swz((uint32_t)(((r0 + arow) << 7) + (kb << 1))));
                    }
                    uint32_t bq[8][2];
#pragma unroll
                    for (int np = 0; np < 4; np++) {
                        uint32_t ro = (uint32_t)(((warpN * 64 + np * 16 + arow) << 7) + (kb << 1));
                        uint32_t r0, r1, r2, r3;
                        ldsm4(r0, r1, r2, r3, Ws + swz(ro));
                        bq[np * 2][0] = r0; bq[np * 2 + 1][0] = r1;
                        bq[np * 2][1] = r2; bq[np * 2 + 1][1] = r3;
                    }
#pragma unroll
                    for (int mb = 0; mb < 4; mb++) {
                        if (warpM * 64 + mb * 16 >= cnt) continue;
#pragma unroll
                        for (int nb = 0; nb < 8; nb++)
                            mma16816(acc[mb][nb], ah[mb], bq[nb]);
                    }
                }
                __syncthreads();
            }
            int obase = (rank - 6) * 256 + warpN * 64;
#pragma unroll
            for (int mb = 0; mb < 4; mb++) {
                int m0 = warpM * 64 + mb * 16 + g;
                int b0 = Slist[m0], b1 = Slist[m0 + 8];
#pragma unroll
                for (int nb = 0; nb < 8; nb++) {
                    float* d = acc[mb][nb];
                    int o = obase + nb * 8 + tg * 2;
                    float2 bb = *(const float2*)(bc + (size_t)ci * On + o);
                    if (b0 >= 0) *(float2*)(g_outT + ((size_t)(t - 1) * Bn + b0) * On + o) =
                        make_float2(sigmoidf(d[0] + bb.x), sigmoidf(d[1] + bb.y));
                    if (b1 >= 0) *(float2*)(g_outT + ((size_t)(t - 1) * Bn + b1) * On + o) =
                        make_float2(sigmoidf(d[2] + bb.x), sigmoidf(d[3] + bb.y));
                }
            }
        }
        CLUSTER_ARRIVE(); CLUSTER_WAIT();    // gh_t visible; A safe to overwrite
    }
}

// ---------------- final transpose: [T][B][O] -> [B][O][T] ----------------
__global__ void transpose_kernel(float* __restrict__ dout) {
    __shared__ float s[32 * 61];
    int b = blockIdx.y, o0 = blockIdx.x * 32, tid = threadIdx.x;
    for (int idx = tid; idx < 32 * Tn; idx += 256) {
        int t = idx >> 5, oi = idx & 31;
        s[oi * 61 + t] = g_outT[((size_t)t * Bn + b) * On + o0 + oi];
    }
    __syncthreads();
    for (int idx = tid; idx < 32 * Tn; idx += 256) {
        int oi = idx / Tn, t = idx % Tn;
        dout[((size_t)b * On + o0 + oi) * Tn + t] = s[oi * 61 + t];
    }
}

// ---------------- launch ----------------
extern "C" void kernel_launch(void* const* d_in, const int* in_sizes, int n_in,
                              void* d_out, int out_size) {
    const float* x    = (const float*)d_in[0];
    const int*   cam  = (const int*)d_in[1];
    const float* W_ih = (const float*)d_in[2];
    const float* W_hh = (const float*)d_in[3];
    const float* b_ih = (const float*)d_in[4];
    const float* b_hh = (const float*)d_in[5];
    const float* Wc   = (const float*)d_in[6];
    const float* bc   = (const float*)d_in[7];
    float* out = (float*)d_out;

    cudaFuncSetAttribute(gi_kernel, cudaFuncAttributeMaxDynamicSharedMemorySize, SMEM_GI);
    cudaFuncSetAttribute(persist_kernel, cudaFuncAttributeMaxDynamicSharedMemorySize, SMEM_P);

    group_kernel<<<1, Bn>>>(cam);
    prep_w_kernel<<<Cn * 2048, 128>>>(W_hh, Wc, W_ih);
    build_ax_kernel<<<Bn, 128>>>(x, cam);
    init_kernel<<<Bn, 256>>>(cam, b_hh);
    gi_kernel<<<Cn * 6, 128, SMEM_GI>>>(b_ih);           // gi = x@W_ih^T + b_ih

    persist_kernel<<<NCTA, 256, SMEM_P>>>(b_hh, bc);     // clustered 60-step recurrence

    transpose_kernel<<<dim3(On / 32, Bn), 256>>>(out);
}